// round 7
// baseline (speedup 1.0000x reference)
#include <cuda_runtime.h>
#include <cstddef>

// Problem constants (from reference setup_inputs)
#define TT   1000
#define BB   8192
#define IN   4
#define HID  10
#define OUT  3
#define BETA 0.95f
#define THR  1.0f

#define NLUT (1 << HID)      // 1024 possible spk1 patterns
#define B3   (BB * OUT)      // floats per timestep per output array

// One thread = one batch element. 128 blocks x 64 threads = 8192 threads.
__global__ __launch_bounds__(64, 1)
void snn_lif_kernel(const float* __restrict__ x,
                    const float* __restrict__ W1,
                    const float* __restrict__ b1,
                    const float* __restrict__ W2,
                    const float* __restrict__ b2,
                    float* __restrict__ out)
{
    // LUT: cur2 = W2 @ spk1 + b2 for every possible spk1 bitmask.
    // Ascending-h subset sum with separately-rounded adds + bias last.
    // Bit-identical to BOTH lowering variants of the 0/1 dot:
    //   fma chain:  fma(1,w,c) = round(w+c), fma(0,w,c) = c
    //   mul+add:    round(1*w) = w, round(w + c);  round(0*w)=±0, c+±0 = c
    __shared__ float4 lut[NLUT];
    for (int m = threadIdx.x; m < NLUT; m += blockDim.x) {
        float c0 = 0.f, c1 = 0.f, c2 = 0.f;
        #pragma unroll
        for (int h = 0; h < HID; ++h) {
            if (m & (1 << h)) {
                c0 = __fadd_rn(c0, W2[0 * HID + h]);
                c1 = __fadd_rn(c1, W2[1 * HID + h]);
                c2 = __fadd_rn(c2, W2[2 * HID + h]);
            }
        }
        c0 = __fadd_rn(c0, b2[0]);
        c1 = __fadd_rn(c1, b2[1]);
        c2 = __fadd_rn(c2, b2[2]);
        lut[m] = make_float4(c0, c1, c2, 0.f);
    }

    // Layer-1 weights in registers (40 + 10 floats).
    float w1[HID][IN], bb1[HID];
    #pragma unroll
    for (int h = 0; h < HID; ++h) {
        bb1[h] = b1[h];
        #pragma unroll
        for (int i = 0; i < IN; ++i) w1[h][i] = W1[h * IN + i];
    }
    __syncthreads();

    const int b = blockIdx.x * blockDim.x + threadIdx.x;  // exact grid: no guard

    // Neuron state in registers.
    float m1[HID], s1[HID];   // layer-1 membrane + previous spike (== reset)
    float m2[OUT], s2[OUT];
    #pragma unroll
    for (int h = 0; h < HID; ++h) { m1[h] = 0.f; s1[h] = 0.f; }
    #pragma unroll
    for (int o = 0; o < OUT; ++o) { m2[o] = 0.f; s2[o] = 0.f; }

    // x is [T, B, 4] -> one float4 per (t, b); stride B float4s per step.
    const float4* __restrict__ xp = reinterpret_cast<const float4*>(x) + b;
    float* __restrict__ out_spk = out + (size_t)b * OUT;                      // spk2_rec
    float* __restrict__ out_mem = out + (size_t)TT * B3 + (size_t)b * OUT;    // mem2_rec

    // Prefetch ring: 4 timesteps ahead (MLP=4 to cover DRAM latency).
    float4 xbuf[4];
    #pragma unroll
    for (int k = 0; k < 4; ++k) xbuf[k] = xp[(size_t)k * BB];

    for (int t = 0; t < TT; t += 4) {
        // Issue next 4 loads early (uniform clamp: tail re-reads t=0..3,
        // values discarded).
        const float4* xq = (t + 4 < TT) ? (xp + (size_t)(t + 4) * BB) : xp;
        float4 nxt[4];
        #pragma unroll
        for (int k = 0; k < 4; ++k) nxt[k] = xq[(size_t)k * BB];

        float* po_s = out_spk + (size_t)t * B3;
        float* po_m = out_mem + (size_t)t * B3;

        #pragma unroll
        for (int k = 0; k < 4; ++k) {
            const float4 xv = xbuf[k];

            // ---- Layer 1: 10 LIF units ----
            unsigned mask = 0;
            #pragma unroll
            for (int h = 0; h < HID; ++h) {
                // Naive XLA loop-fusion dot lowering: ascending k,
                // SEPARATE mul and add roundings (no fma), bias added last.
                float c = __fmul_rn(xv.x, w1[h][0]);
                c = __fadd_rn(c, __fmul_rn(xv.y, w1[h][1]));
                c = __fadd_rn(c, __fmul_rn(xv.z, w1[h][2]));
                c = __fadd_rn(c, __fmul_rn(xv.w, w1[h][3]));
                c = __fadd_rn(c, bb1[h]);
                // Elementwise HLO ops round separately: no fma here either.
                float m = __fadd_rn(__fmul_rn(BETA, m1[h]), c); // beta*mem + cur
                m = __fadd_rn(m, -s1[h]);                        // - reset*THR
                const bool sp = m > THR;
                s1[h] = sp ? 1.0f : 0.0f;
                mask |= (unsigned)sp << h;
                m1[h] = m;
            }

            // ---- Layer 2: cur2 via LUT, 3 LIF units ----
            const float4 cv = lut[mask];
            const float cc[OUT] = { cv.x, cv.y, cv.z };
            #pragma unroll
            for (int o = 0; o < OUT; ++o) {
                float m = __fadd_rn(__fmul_rn(BETA, m2[o]), cc[o]);
                m = __fadd_rn(m, -s2[o]);
                const bool sp = m > THR;
                const float spf = sp ? 1.0f : 0.0f;
                s2[o] = spf;
                m2[o] = m;
                po_s[(size_t)k * B3 + o] = spf;   // spk2_rec[t+k, b, o]
                po_m[(size_t)k * B3 + o] = m;     // mem2_rec[t+k, b, o]
            }
        }

        #pragma unroll
        for (int k = 0; k < 4; ++k) xbuf[k] = nxt[k];
    }
}

extern "C" void kernel_launch(void* const* d_in, const int* in_sizes, int n_in,
                              void* d_out, int out_size)
{
    const float* x  = (const float*)d_in[0];   // [1000, 8192, 4]
    const float* W1 = (const float*)d_in[1];   // [10, 4]
    const float* b1 = (const float*)d_in[2];   // [10]
    const float* W2 = (const float*)d_in[3];   // [3, 10]
    const float* b2 = (const float*)d_in[4];   // [3]
    float* out = (float*)d_out;                // [spk2_rec | mem2_rec], each [1000,8192,3]

    snn_lif_kernel<<<BB / 64, 64>>>(x, W1, b1, W2, b2, out);
}

// round 8
// speedup vs baseline: 1.1682x; 1.1682x over previous
#include <cuda_runtime.h>
#include <cstddef>

// Problem constants (from reference setup_inputs)
#define TT   1000
#define BB   8192
#define IN   4
#define HID  10
#define OUT  3
#define BETA 0.95f
#define THR  1.0f

#define NLUT (1 << HID)      // 1024 possible spk1 patterns
#define B3   (BB * OUT)      // floats per timestep per output array
#define HHALF 5              // hidden units per thread-half

// Two threads per batch element. 128 blocks x 128 threads = 16384 threads.
// Even lane = half 0 (hidden units 0-4, writes spk2), odd lane = half 1
// (hidden units 5-9, writes mem2). Masks combined via shfl_xor(1).
__global__ __launch_bounds__(128, 1)
void snn_lif_kernel(const float* __restrict__ x,
                    const float* __restrict__ W1,
                    const float* __restrict__ b1,
                    const float* __restrict__ W2,
                    const float* __restrict__ b2,
                    float* __restrict__ out)
{
    // LUT: cur2 = W2 @ spk1 + b2 for every possible spk1 bitmask.
    // Ascending-h subset sum, separately-rounded adds, bias last —
    // bit-identical to the reference 0/1 dot under fma OR mul+add lowering.
    __shared__ float4 lut[NLUT];
    for (int m = threadIdx.x; m < NLUT; m += blockDim.x) {
        float c0 = 0.f, c1 = 0.f, c2 = 0.f;
        #pragma unroll
        for (int h = 0; h < HID; ++h) {
            if (m & (1 << h)) {
                c0 = __fadd_rn(c0, W2[0 * HID + h]);
                c1 = __fadd_rn(c1, W2[1 * HID + h]);
                c2 = __fadd_rn(c2, W2[2 * HID + h]);
            }
        }
        c0 = __fadd_rn(c0, b2[0]);
        c1 = __fadd_rn(c1, b2[1]);
        c2 = __fadd_rn(c2, b2[2]);
        lut[m] = make_float4(c0, c1, c2, 0.f);
    }

    const int tid  = blockIdx.x * blockDim.x + threadIdx.x;
    const int e    = tid >> 1;        // batch element
    const int half = tid & 1;         // which 5 hidden units
    const int hbase = half * HHALF;   // global unit index offset

    // This half's layer-1 weights in registers (20 + 5 floats).
    float w1[HHALF][IN], bb1[HHALF];
    #pragma unroll
    for (int j = 0; j < HHALF; ++j) {
        bb1[j] = b1[hbase + j];
        #pragma unroll
        for (int i = 0; i < IN; ++i) w1[j][i] = W1[(hbase + j) * IN + i];
    }
    __syncthreads();

    // Neuron state: membranes in fp regs, prev-spike (== reset) as bools.
    float m1[HHALF]; bool p1[HHALF];
    float m2[OUT];   bool p2[OUT];
    #pragma unroll
    for (int j = 0; j < HHALF; ++j) { m1[j] = 0.f; p1[j] = false; }
    #pragma unroll
    for (int o = 0; o < OUT; ++o)   { m2[o] = 0.f; p2[o] = false; }

    // x is [T, B, 4] -> one float4 per (t, e). Both halves read the same
    // float4 (second hit dedups in L1).
    const float4* __restrict__ xp = reinterpret_cast<const float4*>(x) + e;
    // half 0 -> spk2_rec (offset 0), half 1 -> mem2_rec (offset TT*B3).
    float* __restrict__ po = out + (size_t)half * TT * B3 + (size_t)e * OUT;

    // Prefetch ring: 4 timesteps ahead.
    float4 xbuf[4];
    #pragma unroll
    for (int k = 0; k < 4; ++k) xbuf[k] = xp[(size_t)k * BB];

    for (int t = 0; t < TT; t += 4) {
        // Issue next 4 loads early (tail clamps to t=0..3; values discarded).
        const float4* xq = (t + 4 < TT) ? (xp + (size_t)(t + 4) * BB) : xp;
        float4 nxt[4];
        #pragma unroll
        for (int k = 0; k < 4; ++k) nxt[k] = xq[(size_t)k * BB];

        #pragma unroll
        for (int k = 0; k < 4; ++k) {
            const float4 xv = xbuf[k];

            // ---- Layer 1: this half's 5 LIF units ----
            unsigned mask = 0;
            #pragma unroll
            for (int j = 0; j < HHALF; ++j) {
                // Ascending-k, separate mul/add roundings (no fma), bias last.
                float c = __fmul_rn(xv.x, w1[j][0]);
                c = __fadd_rn(c, __fmul_rn(xv.y, w1[j][1]));
                c = __fadd_rn(c, __fmul_rn(xv.z, w1[j][2]));
                c = __fadd_rn(c, __fmul_rn(xv.w, w1[j][3]));
                c = __fadd_rn(c, bb1[j]);
                float m = __fadd_rn(__fmul_rn(BETA, m1[j]), c); // beta*mem + cur
                if (p1[j]) m = __fadd_rn(m, -1.0f);             // reset (thr=1)
                const bool sp = m > THR;
                p1[j] = sp;
                if (sp) mask |= 1u << (hbase + j);
                m1[j] = m;
            }
            // Combine the two halves' masks (pair = adjacent lanes).
            mask |= __shfl_xor_sync(0xFFFFFFFFu, mask, 1);

            // ---- Layer 2: cur2 via LUT, 3 LIF units (both halves compute;
            //      half 0 stores spikes, half 1 stores membranes) ----
            const float4 cv = lut[mask];
            const float cc[OUT] = { cv.x, cv.y, cv.z };
            float* pk = po + (size_t)(t + k) * B3;
            #pragma unroll
            for (int o = 0; o < OUT; ++o) {
                float m = __fadd_rn(__fmul_rn(BETA, m2[o]), cc[o]);
                if (p2[o]) m = __fadd_rn(m, -1.0f);
                const bool sp = m > THR;
                p2[o] = sp;
                m2[o] = m;
                pk[o] = half ? m : (sp ? 1.0f : 0.0f);
            }
        }

        #pragma unroll
        for (int k = 0; k < 4; ++k) xbuf[k] = nxt[k];
    }
}

extern "C" void kernel_launch(void* const* d_in, const int* in_sizes, int n_in,
                              void* d_out, int out_size)
{
    const float* x  = (const float*)d_in[0];   // [1000, 8192, 4]
    const float* W1 = (const float*)d_in[1];   // [10, 4]
    const float* b1 = (const float*)d_in[2];   // [10]
    const float* W2 = (const float*)d_in[3];   // [3, 10]
    const float* b2 = (const float*)d_in[4];   // [3]
    float* out = (float*)d_out;                // [spk2_rec | mem2_rec]

    snn_lif_kernel<<<(BB * 2) / 128, 128>>>(x, W1, b1, W2, b2, out);
}